// round 7
// baseline (speedup 1.0000x reference)
#include <cuda_runtime.h>
#include <cstdint>
#include <cstddef>

#define RES_C     128
#define BATCH     4
#define T_START   8192
#define NBLK      40
#define SKIP_SIZE 4096

#define TN        32
#define NTHREADS  256            // 8 warps, 3 CTAs/SM

#define XP        256            // X row pitch (floats)
#define GPCH      128            // G row pitch

// smem (float offsets): X 32x256 (32KB), 2 x 16KB weight bufs
#define REGX      0
#define REGW      8192
#define WCHUNK    4096           // 16KB chunk [128o][32k]
#define SMEM_FLOATS 16384
#define SMEM_BYTES  (SMEM_FLOATS * 4)   // 65536

#define WBLK_FLOATS 32768        // per block per stage-group (8 chunks)

static const int H_DIL[NBLK] = {
    1,2,4,8,16,32,64,128,256,512,
    1,2,4,8,16,32,64,128,256,512,
    1,2,4,8,16,32,64,128,256,512,
    1,2,4,8,16,32,64,128,256,512};

// ---------------- device scratch ----------------
__device__ float g_bufA[BATCH * RES_C * T_START];
__device__ float g_bufB[BATCH * RES_C * T_START];
__device__ float g_w1[NBLK * WBLK_FLOATS];   // 8 chunks [o128][k32] packed+swizzled
__device__ float g_w2[NBLK * WBLK_FLOATS];   // interleaved chunks: r0,s0,r1,s1,... 16KB each

// ---------------- layout helpers ----------------
__host__ __device__ __forceinline__ int packc(int k) {
    return ((k >> 4) << 4) | ((k & 3) << 2) | ((k & 15) >> 2);
}
__host__ __device__ __forceinline__ int fsw(int r) {
    return ((r & 1) << 4) | ((r & 6) << 1);
}

__device__ __forceinline__ uint32_t tf32u(float x) {
    uint32_t u;
    asm("cvt.rna.tf32.f32 %0, %1;" : "=r"(u) : "f"(x));
    return u;
}
__device__ __forceinline__ float tf32f(float x) { return __uint_as_float(tf32u(x)); }

__device__ __forceinline__ void mma8(float c[4], uint32_t a0, uint32_t a1, uint32_t a2,
                                     uint32_t a3, uint32_t b0, uint32_t b1) {
    asm volatile(
        "mma.sync.aligned.m16n8k8.row.col.f32.tf32.tf32.f32 "
        "{%0,%1,%2,%3}, {%4,%5,%6,%7}, {%8,%9}, {%0,%1,%2,%3};\n"
        : "+f"(c[0]), "+f"(c[1]), "+f"(c[2]), "+f"(c[3])
        : "r"(a0), "r"(a1), "r"(a2), "r"(a3), "r"(b0), "r"(b1));
}

__device__ __forceinline__ void lds128(uint32_t r[4], uint32_t addr) {
    asm volatile("ld.shared.v4.b32 {%0,%1,%2,%3}, [%4];"
                 : "=r"(r[0]), "=r"(r[1]), "=r"(r[2]), "=r"(r[3]) : "r"(addr));
}

__device__ __forceinline__ float gate_fn(float y) {
    float u = __expf(-fabsf(y));
    float a = (1.f - u) * __frcp_rn(1.f + u * u);
    return (y >= 0.f) ? a : -u * a;
}

#define CPWAIT0() asm volatile("cp.async.wait_group 0;\n")

// ---------------- weight prep (layouts identical to round 6) ----------------
__global__ void prep_w1(const float* __restrict__ w, float* __restrict__ out, int n) {
    int i = blockIdx.x * blockDim.x + threadIdx.x;
    if (i >= n) return;
    int kl  = i & 31;
    int o   = (i >> 5) & 127;
    int ch  = (i >> 12) & 7;
    int blk = i >> 15;
    int kg  = ch * 32 + kl;
    float v = (kg < 128) ? w[(((blk * 128 + o) * 128) + kg) * 2 + 0]
                         : w[(((blk * 128 + o) * 128) + (kg - 128)) * 2 + 1];
    out[(size_t)blk * WBLK_FLOATS + ch * WCHUNK + o * 32 + (packc(kl) ^ fsw(o))] = tf32f(v);
}
__global__ void prep_w2(const float* __restrict__ wr, const float* __restrict__ ws,
                        float* __restrict__ out, int n) {
    int i = blockIdx.x * blockDim.x + threadIdx.x;
    if (i >= n) return;
    int kl  = i & 31;
    int o   = (i >> 5) & 127;
    int h   = (i >> 12) & 1;     // 0 = res, 1 = skip
    int pr  = (i >> 13) & 3;     // k-chunk
    int blk = i >> 15;
    float v = (h == 0) ? wr[((blk * 128 + o) * 128) + pr * 32 + kl]
                       : ws[((blk * 128 + o) * 128) + pr * 32 + kl];
    out[(size_t)blk * WBLK_FLOATS + (2 * pr + h) * WCHUNK + o * 32 + (packc(kl) ^ fsw(o))]
        = tf32f(v);
}

// ---------------- fused per-block kernel ----------------
__global__ __launch_bounds__(NTHREADS, 3)
void wavenet_block(const float* __restrict__ xin, float* __restrict__ xout,
                   float* __restrict__ skip,
                   const float* __restrict__ w1g, const float* __restrict__ w2g,
                   const float* __restrict__ brs, const float* __restrict__ bsk,
                   int Tc, int d, int L, int sstart)
{
    extern __shared__ float sm[];
    const uint32_t sb = (uint32_t)__cvta_generic_to_shared(sm);

    const int tid  = threadIdx.x;
    const int lane = tid & 31;
    const int wid  = tid >> 5;
    const int g    = lane >> 2;
    const int tg   = lane & 3;
    const int tg4  = tg << 2;
    const int fg   = fsw(g);
    const int t0   = blockIdx.x * TN;
    const int b    = blockIdx.y;

    const int wm = (wid & 1) * 16;    // time tile (16 rows per warp)
    const int wn = (wid >> 1) * 32;   // out tile

    const bool full      = (t0 + TN <= L);
    const bool need_skip = (t0 + TN > sstart);
    const int  nph2      = need_skip ? 8 : 4;

    // ---- 16KB chunk fetch into slot (0/1) ----
    auto fetchp = [&](const float* src, int slot) {
        uint32_t dst = sb + (REGW + slot * WCHUNK) * 4;
        #pragma unroll
        for (int i = 0; i < 4; ++i) {
            int e = tid + i * NTHREADS;
            asm volatile("cp.async.cg.shared.global [%0], [%1], 16;\n"
                         :: "r"(dst + e * 16), "l"(src + e * 4));
        }
        asm volatile("cp.async.commit_group;\n");
    };

    fetchp(w1g, 0);

    // ---- X tile: 32 rows x 256 k, packed+swizzled, tf32 ----
    const float* xb = xin + (size_t)b * RES_C * Tc;
    {
        const int t   = tid & 31;
        const int grp = tid >> 5;            // 0..7, 32 k's each
        const int tt  = t0 + t;
        const int ft  = fsw(t);
        const uint32_t xrow = sb + (REGX + t * XP) * 4;
        if (full) {
            #pragma unroll
            for (int idx = 0; idx < 8; ++idx) {
                const int kb    = grp * 32 + (idx >> 2) * 16 + (idx & 3);
                const int cbase = grp * 32 + (idx >> 2) * 16 + (idx & 3) * 4;
                uint32_t u[4];
                #pragma unroll
                for (int j = 0; j < 4; ++j) {
                    const int k = kb + 4 * j;
                    float v = (k < 128) ? xb[(size_t)k * Tc + tt]
                                        : xb[(size_t)(k - 128) * Tc + tt + d];
                    u[j] = tf32u(v);
                }
                asm volatile("st.shared.v4.b32 [%0], {%1,%2,%3,%4};"
                             :: "r"(xrow + (uint32_t)((cbase ^ ft) << 2)),
                                "r"(u[0]), "r"(u[1]), "r"(u[2]), "r"(u[3]));
            }
        } else {
            #pragma unroll
            for (int idx = 0; idx < 8; ++idx) {
                const int kb    = grp * 32 + (idx >> 2) * 16 + (idx & 3);
                const int cbase = grp * 32 + (idx >> 2) * 16 + (idx & 3) * 4;
                uint32_t u[4];
                #pragma unroll
                for (int j = 0; j < 4; ++j) {
                    const int k = kb + 4 * j;
                    float v = 0.f;
                    if (k < 128) { if (tt < Tc) v = xb[(size_t)k * Tc + tt]; }
                    else         { if (tt < L)  v = xb[(size_t)(k - 128) * Tc + tt + d]; }
                    u[j] = tf32u(v);
                }
                asm volatile("st.shared.v4.b32 [%0], {%1,%2,%3,%4};"
                             :: "r"(xrow + (uint32_t)((cbase ^ ft) << 2)),
                                "r"(u[0]), "r"(u[1]), "r"(u[2]), "r"(u[3]));
            }
        }
    }

    const uint32_t xRow = sb + (REGX + (wm + g) * XP) * 4;
    const uint32_t gRow = sb + (REGX + (wm + g) * GPCH) * 4;

    // ================= stage 1: 8 phases of KC=32 =================
    float acc1[4][4];
    #pragma unroll
    for (int j = 0; j < 4; ++j)
        #pragma unroll
        for (int q = 0; q < 4; ++q) acc1[j][q] = 0.f;

    #pragma unroll 1
    for (int p = 0; p < 8; ++p) {
        CPWAIT0();
        __syncthreads();
        if (p < 7) fetchp(w1g + (p + 1) * WCHUNK, (p + 1) & 1);
        else       fetchp(w2g, 0);                 // first stage-2 chunk (res0)
        const uint32_t wbuf = sb + (REGW + (p & 1) * WCHUNK) * 4;
        const int kb = p * 32;
        #pragma unroll
        for (int P = 0; P < 2; ++P) {
            const int col  = ((kb + P * 16 + tg4) ^ fg) << 2;
            const int colw = ((P * 16 + tg4) ^ fg) << 2;
            uint32_t A0[4], A1[4], Bf[4][4];
            lds128(A0, xRow + col);
            lds128(A1, xRow + 8 * XP * 4 + col);
            #pragma unroll
            for (int nt = 0; nt < 4; ++nt)
                lds128(Bf[nt], wbuf + (uint32_t)(wn + nt * 8 + g) * (32 * 4) + colw);
            #pragma unroll
            for (int nt = 0; nt < 4; ++nt) {
                mma8(acc1[nt], A0[0], A1[0], A0[1], A1[1], Bf[nt][0], Bf[nt][1]);
                mma8(acc1[nt], A0[2], A1[2], A0[3], A1[3], Bf[nt][2], Bf[nt][3]);
            }
        }
    }

    // ---- gate: acc1 -> G (pitch 128, overwrites dead X rows) ----
    __syncthreads();     // all stage-1 X reads complete
    #pragma unroll
    for (int nt = 0; nt < 4; ++nt) {
        const int t = wm + g;
        const int o = wn + nt * 8 + 2 * tg;
        const int c0 = packc(o)     ^ fsw(t);
        const int c1 = packc(o + 1) ^ fsw(t);
        float* cc = acc1[nt];
        sm[REGX + t * GPCH + c0]       = tf32f(gate_fn(cc[0]));
        sm[REGX + t * GPCH + c1]       = tf32f(gate_fn(cc[1]));
        sm[REGX + (t + 8) * GPCH + c0] = tf32f(gate_fn(cc[2]));
        sm[REGX + (t + 8) * GPCH + c1] = tf32f(gate_fn(cc[3]));
    }

    // ================= stage 2: nph2 phases of KC=32 =================
    float acc2[4][4], acc3[4][4];
    #pragma unroll
    for (int j = 0; j < 4; ++j)
        #pragma unroll
        for (int q = 0; q < 4; ++q) { acc2[j][q] = 0.f; acc3[j][q] = 0.f; }

    #pragma unroll 1
    for (int s = 0; s < nph2; ++s) {
        CPWAIT0();
        __syncthreads();   // s==0 also publishes gate writes
        if (s + 1 < nph2) {
            const int nidx = need_skip ? (s + 1) : 2 * (s + 1);
            fetchp(w2g + nidx * WCHUNK, (s + 1) & 1);
        }
        const uint32_t wbuf = sb + (REGW + (s & 1) * WCHUNK) * 4;
        const int kb = (need_skip ? (s >> 1) : s) * 32;
        const bool isskip = need_skip && (s & 1);
        #pragma unroll
        for (int P = 0; P < 2; ++P) {
            const int col  = ((kb + P * 16 + tg4) ^ fg) << 2;
            const int colw = ((P * 16 + tg4) ^ fg) << 2;
            uint32_t A0[4], A1[4], Bf[4][4];
            lds128(A0, gRow + col);
            lds128(A1, gRow + 8 * GPCH * 4 + col);
            #pragma unroll
            for (int nt = 0; nt < 4; ++nt)
                lds128(Bf[nt], wbuf + (uint32_t)(wn + nt * 8 + g) * (32 * 4) + colw);
            if (isskip) {
                #pragma unroll
                for (int nt = 0; nt < 4; ++nt) {
                    mma8(acc3[nt], A0[0], A1[0], A0[1], A1[1], Bf[nt][0], Bf[nt][1]);
                    mma8(acc3[nt], A0[2], A1[2], A0[3], A1[3], Bf[nt][2], Bf[nt][3]);
                }
            } else {
                #pragma unroll
                for (int nt = 0; nt < 4; ++nt) {
                    mma8(acc2[nt], A0[0], A1[0], A0[1], A1[1], Bf[nt][0], Bf[nt][1]);
                    mma8(acc2[nt], A0[2], A1[2], A0[3], A1[3], Bf[nt][2], Bf[nt][3]);
                }
            }
        }
    }

    // ---- res epilogue: direct STG from accumulators ----
    #pragma unroll
    for (int nt = 0; nt < 4; ++nt) {
        const int t = wm + g;
        const int o = wn + nt * 8 + 2 * tg;
        const float b0 = __ldg(brs + o);
        const float b1 = __ldg(brs + o + 1);
        const size_t r0 = (size_t)(b * 128 + o) * L;
        const size_t x0 = (size_t)o * Tc;
        float* cc = acc2[nt];
        if (full) {
            xout[r0 + t0 + t]         = cc[0] + b0 + xb[x0 + t0 + t + d];
            xout[r0 + L + t0 + t]     = cc[1] + b1 + xb[x0 + Tc + t0 + t + d];
            xout[r0 + t0 + t + 8]     = cc[2] + b0 + xb[x0 + t0 + t + 8 + d];
            xout[r0 + L + t0 + t + 8] = cc[3] + b1 + xb[x0 + Tc + t0 + t + 8 + d];
        } else {
            if (t0 + t < L) {
                xout[r0 + t0 + t]     = cc[0] + b0 + xb[x0 + t0 + t + d];
                xout[r0 + L + t0 + t] = cc[1] + b1 + xb[x0 + Tc + t0 + t + d];
            }
            if (t0 + t + 8 < L) {
                xout[r0 + t0 + t + 8]     = cc[2] + b0 + xb[x0 + t0 + t + 8 + d];
                xout[r0 + L + t0 + t + 8] = cc[3] + b1 + xb[x0 + Tc + t0 + t + 8 + d];
            }
        }
    }

    // ---- skip epilogue ----
    if (need_skip) {
        const bool wfull = full && (t0 >= sstart);
        #pragma unroll
        for (int nt = 0; nt < 4; ++nt) {
            const int t = wm + g;
            const int o = wn + nt * 8 + 2 * tg;
            const float b0 = __ldg(bsk + o);
            const float b1 = __ldg(bsk + o + 1);
            const size_t r0 = (size_t)(b * 128 + o) * SKIP_SIZE - sstart;
            float* cc = acc3[nt];
            if (wfull) {
                skip[r0 + t0 + t]                 = cc[0] + b0;
                skip[r0 + SKIP_SIZE + t0 + t]     = cc[1] + b1;
                skip[r0 + t0 + t + 8]             = cc[2] + b0;
                skip[r0 + SKIP_SIZE + t0 + t + 8] = cc[3] + b1;
            } else {
                const int tt0 = t0 + t, tt1 = t0 + t + 8;
                if (tt0 >= sstart && tt0 < L) {
                    skip[r0 + tt0]             = cc[0] + b0;
                    skip[r0 + SKIP_SIZE + tt0] = cc[1] + b1;
                }
                if (tt1 >= sstart && tt1 < L) {
                    skip[r0 + tt1]             = cc[2] + b0;
                    skip[r0 + SKIP_SIZE + tt1] = cc[3] + b1;
                }
            }
        }
    }

    CPWAIT0();   // drain before CTA exit
}

// ---------------- host launcher ----------------
extern "C" void kernel_launch(void* const* d_in, const int* in_sizes, int n_in,
                              void* d_out, int out_size) {
    (void)in_sizes; (void)n_in; (void)out_size;

    const float* x     = (const float*)d_in[0];
    const float* wdil  = (const float*)d_in[1];
    const float* wres  = (const float*)d_in[2];
    const float* bres  = (const float*)d_in[3];
    const float* wskip = (const float*)d_in[4];
    const float* bskip = (const float*)d_in[5];
    float* out = (float*)d_out;

    float *bufA, *bufB, *w1, *w2;
    cudaGetSymbolAddress((void**)&bufA, g_bufA);
    cudaGetSymbolAddress((void**)&bufB, g_bufB);
    cudaGetSymbolAddress((void**)&w1,   g_w1);
    cudaGetSymbolAddress((void**)&w2,   g_w2);

    cudaFuncSetAttribute(wavenet_block, cudaFuncAttributeMaxDynamicSharedMemorySize, SMEM_BYTES);

    const int n1 = NBLK * WBLK_FLOATS;
    prep_w1<<<(n1 + 255) / 256, 256>>>(wdil, w1, n1);
    prep_w2<<<(n1 + 255) / 256, 256>>>(wres, wskip, w2, n1);

    int Tc = T_START;
    const float* cur = x;
    float* nxt = bufA;
    for (int blk = 0; blk < NBLK; ++blk) {
        const int d = H_DIL[blk];
        const int L = Tc - d;
        dim3 grid((L + TN - 1) / TN, BATCH);
        wavenet_block<<<grid, NTHREADS, SMEM_BYTES>>>(
            cur, nxt,
            out + (size_t)blk * BATCH * RES_C * SKIP_SIZE,
            w1 + (size_t)blk * WBLK_FLOATS,
            w2 + (size_t)blk * WBLK_FLOATS,
            bres + blk * 128, bskip + blk * 128,
            Tc, d, L, L - SKIP_SIZE);
        cur = nxt;
        nxt = (nxt == bufA) ? bufB : bufA;
        Tc = L;
    }
}